// round 13
// baseline (speedup 1.0000x reference)
#include <cuda_runtime.h>
#include <cuda_fp16.h>
#include <cstdint>

#define N_NODES 50000
#define E_EDGES 800000
#define IN_DIM  128
#define OUT_DIM 64
#define HEADS   4
#define HC      256      // HEADS*OUT_DIM
#define Q_HID   32
#define NEG_SLOPE 0.2f

// ---------------- scratch (static device memory; no allocations) ----------------
__device__ __align__(16) __half g_hh[N_NODES * HC];     // 25.6 MB  h = x@W (fp16)
__device__ __align__(16) __half g_xh[N_NODES * IN_DIM]; // 12.8 MB  x in fp16
__device__ __align__(16) __half g_whT2[8 * 256 * 16];   // W^T fp16, chunked
__device__ __align__(16) float g_asrc[N_NODES * HEADS];
__device__ __align__(16) float g_adst[N_NODES * HEADS];
__device__ __align__(16) float g_exp[E_EDGES * HEADS];  // exp(alpha), CSR-permuted
__device__ __align__(16) float g_acc[N_NODES * OUT_DIM];
__device__ __align__(16) float g_v[64 * HEADS];
__device__ __align__(16) float g_wq2v[Q_HID * HEADS];
__device__ __align__(16) float g_bq2v[HEADS];
__device__ float g_t[OUT_DIM];
__device__ int   g_src[E_EDGES];
__device__ int   g_dst[E_EDGES];
// CSR by destination
__device__ int   g_cnt[N_NODES];
__device__ int   g_rowptr[N_NODES + 1];
__device__ int   g_cur[N_NODES];
__device__ int   g_cs[E_EDGES];     // src, CSR order
__device__ int   g_epos[E_EDGES];   // edge -> CSR slot

// ---------------- K_convert: detect int32/int64, expand indices, zero cnt ------
__global__ void k_convert(const void* __restrict__ ei) {
    __shared__ int s_is64;
    if (threadIdx.x == 0) {
        const int* p = (const int*)ei;
        int zeros = 0;
        for (int i = 1; i < 256; i += 2) zeros += (p[i] == 0);
        s_is64 = (zeros > 64);
    }
    __syncthreads();
    int i = blockIdx.x * blockDim.x + threadIdx.x;
    if (i < N_NODES) g_cnt[i] = 0;
    if (i >= E_EDGES) return;
    if (s_is64) {
        const long long* p = (const long long*)ei;
        g_src[i] = (int)p[i];
        g_dst[i] = (int)p[E_EDGES + i];
    } else {
        const int* p = (const int*)ei;
        g_src[i] = p[i];
        g_dst[i] = p[E_EDGES + i];
    }
}

// ---------------- CSR build ----------------------------------------------------
__global__ void k_hist() {
    int e = blockIdx.x * blockDim.x + threadIdx.x;
    if (e < E_EDGES) atomicAdd(&g_cnt[g_dst[e]], 1);
}

__global__ void k_scan() {   // exclusive prefix, single 1024-thread block
    __shared__ int part[1024];
    const int CH = (N_NODES + 1023) / 1024;  // 49
    int t = threadIdx.x;
    int base = t * CH;
    int lim = N_NODES - base; if (lim > CH) lim = CH; if (lim < 0) lim = 0;
    int s = 0;
    for (int i = 0; i < lim; ++i) s += g_cnt[base + i];
    part[t] = s;
    __syncthreads();
    for (int off = 1; off < 1024; off <<= 1) {
        int v = (t >= off) ? part[t - off] : 0;
        __syncthreads();
        part[t] += v;
        __syncthreads();
    }
    int run = part[t] - s;
    for (int i = 0; i < lim; ++i) {
        int idx = base + i;
        g_rowptr[idx] = run;
        g_cur[idx] = run;
        run += g_cnt[idx];
    }
    if (t == 1023) g_rowptr[N_NODES] = E_EDGES;
}

__global__ void k_scatter() {
    int e = blockIdx.x * blockDim.x + threadIdx.x;
    if (e >= E_EDGES) return;
    int pos = atomicAdd(&g_cur[g_dst[e]], 1);
    g_cs[pos] = g_src[e];
    g_epos[e] = pos;
}

// ---------------- K_wcvt: W -> fp16, transposed + chunked [kc][n][ki] ----------
__global__ void k_wcvt(const float* __restrict__ W) {
    int i = blockIdx.x * blockDim.x + threadIdx.x;   // 32768
    if (i >= 8 * 256 * 16) return;
    int kc = i >> 12, r = i & 4095;
    int n = r >> 4, ki = r & 15;
    g_whT2[i] = __float2half_rn(W[(kc * 16 + ki) * HC + n]);
}

// ---------------- K_xcvt: pure x -> fp16 convert (8 floats/thread) ------------
__global__ void k_xcvt(const float* __restrict__ x) {
    int i = blockIdx.x * blockDim.x + threadIdx.x;
    if (i >= N_NODES * IN_DIM / 8) return;
    const float4* xp = (const float4*)x;
    float4 a = __ldcs(&xp[i * 2]);
    float4 b = __ldcs(&xp[i * 2 + 1]);
    __half2 h0 = __floats2half2_rn(a.x, a.y), h1 = __floats2half2_rn(a.z, a.w);
    __half2 h2 = __floats2half2_rn(b.x, b.y), h3 = __floats2half2_rn(b.z, b.w);
    uint4 u;
    u.x = *(uint32_t*)&h0; u.y = *(uint32_t*)&h1;
    u.z = *(uint32_t*)&h2; u.w = *(uint32_t*)&h3;
    *(uint4*)&g_xh[i * 8] = u;
}

// ---------------- K1: tensor-core GEMM + fused EXACT fp32 attention logits ----
__device__ __forceinline__ void mma16816(float* c, const uint32_t* a,
                                         uint32_t b0, uint32_t b1) {
    asm volatile(
        "mma.sync.aligned.m16n8k16.row.col.f32.f16.f16.f32 "
        "{%0,%1,%2,%3}, {%4,%5,%6,%7}, {%8,%9}, {%0,%1,%2,%3};\n"
        : "+f"(c[0]), "+f"(c[1]), "+f"(c[2]), "+f"(c[3])
        : "r"(a[0]), "r"(a[1]), "r"(a[2]), "r"(a[3]), "r"(b0), "r"(b1));
}

__global__ __launch_bounds__(256) void k1_mma(const float* __restrict__ att_src,
                                              const float* __restrict__ att_dst) {
    __shared__ __half as[64][136];   // A tile, padded
    __shared__ __half ws[256][24];   // W chunk [n][k16], padded
    __shared__ float s_att[64][8];   // [row][head: src 0-3 | dst 4-7]
    int t = threadIdx.x, lane = t & 31, w = t >> 5;
    int wm = w & 1, wn = w >> 1;     // wn == head (64-col span)
    int g = lane >> 2, tg = lane & 3;
    int blk = blockIdx.x;

    {   // stage A tile (64 rows x 128 halves)
        int r = t >> 2, part = t & 3;
        int node = blk * 64 + r;
        uint4 z = make_uint4(0, 0, 0, 0);
        uint4* dst = (uint4*)&as[r][part * 32];
        if (node < N_NODES) {
            const uint4* srcp = (const uint4*)&g_xh[node * IN_DIM + part * 32];
            dst[0] = srcp[0]; dst[1] = srcp[1]; dst[2] = srcp[2]; dst[3] = srcp[3];
        } else {
            dst[0] = z; dst[1] = z; dst[2] = z; dst[3] = z;
        }
    }

    float acc[2][8][4];
    #pragma unroll
    for (int mt = 0; mt < 2; ++mt)
        #pragma unroll
        for (int nt = 0; nt < 8; ++nt)
            #pragma unroll
            for (int i = 0; i < 4; ++i) acc[mt][nt][i] = 0.f;

    for (int kc = 0; kc < 8; ++kc) {
        __syncthreads();
        {   // stage W chunk (8KB contiguous, coalesced)
            const uint4* srcp = (const uint4*)&g_whT2[kc * 4096];
            uint4 w0 = srcp[t * 2], w1 = srcp[t * 2 + 1];
            *(uint4*)&ws[t][0] = w0;
            *(uint4*)&ws[t][8] = w1;
        }
        __syncthreads();
        uint32_t a[2][4];
        #pragma unroll
        for (int mt = 0; mt < 2; ++mt) {
            int r = wm * 32 + mt * 16 + g;
            int kb = kc * 16 + tg * 2;
            a[mt][0] = *(const uint32_t*)&as[r][kb];
            a[mt][1] = *(const uint32_t*)&as[r + 8][kb];
            a[mt][2] = *(const uint32_t*)&as[r][kb + 8];
            a[mt][3] = *(const uint32_t*)&as[r + 8][kb + 8];
        }
        #pragma unroll
        for (int nt = 0; nt < 8; ++nt) {
            int n = wn * 64 + nt * 8 + g;
            uint32_t b0 = *(const uint32_t*)&ws[n][tg * 2];
            uint32_t b1 = *(const uint32_t*)&ws[n][tg * 2 + 8];
            mma16816(acc[0][nt], a[0], b0, b1);
            mma16816(acc[1][nt], a[1], b0, b1);
        }
    }

    // ---- fp16 store of h ----
    #pragma unroll
    for (int mt = 0; mt < 2; ++mt) {
        int r = blk * 64 + wm * 32 + mt * 16 + g;
        #pragma unroll
        for (int nt = 0; nt < 8; ++nt) {
            int col = wn * 64 + nt * 8 + tg * 2;
            if (r < N_NODES) {
                __half2 h01 = __floats2half2_rn(acc[mt][nt][0], acc[mt][nt][1]);
                *(uint32_t*)&g_hh[r * HC + col] = *(uint32_t*)&h01;
            }
            if (r + 8 < N_NODES) {
                __half2 h23 = __floats2half2_rn(acc[mt][nt][2], acc[mt][nt][3]);
                *(uint32_t*)&g_hh[(r + 8) * HC + col] = *(uint32_t*)&h23;
            }
        }
    }

    // ---- exact fp32 attention logits from the accumulators ----
    float2 asv[8], adv[8];
    #pragma unroll
    for (int nt = 0; nt < 8; ++nt) {
        int col = wn * 64 + nt * 8 + tg * 2;
        asv[nt] = *(const float2*)&att_src[col];
        adv[nt] = *(const float2*)&att_dst[col];
    }
    #pragma unroll
    for (int mt = 0; mt < 2; ++mt) {
        #pragma unroll
        for (int half = 0; half < 2; ++half) {
            float ps = 0.f, pd = 0.f;
            #pragma unroll
            for (int nt = 0; nt < 8; ++nt) {
                float c0 = acc[mt][nt][half * 2], c1 = acc[mt][nt][half * 2 + 1];
                ps += c0 * asv[nt].x + c1 * asv[nt].y;
                pd += c0 * adv[nt].x + c1 * adv[nt].y;
            }
            ps += __shfl_xor_sync(0xffffffffu, ps, 1);
            ps += __shfl_xor_sync(0xffffffffu, ps, 2);
            pd += __shfl_xor_sync(0xffffffffu, pd, 1);
            pd += __shfl_xor_sync(0xffffffffu, pd, 2);
            if (tg == 0) {
                int rl = wm * 32 + mt * 16 + g + half * 8;
                s_att[rl][wn] = ps;
                s_att[rl][4 + wn] = pd;
            }
        }
    }
    __syncthreads();
    if (t < 64) {
        int node = blk * 64 + t;
        if (node < N_NODES) {
            *(float4*)&g_asrc[node * 4] = *(const float4*)&s_att[t][0];
            *(float4*)&g_adst[node * 4] = *(const float4*)&s_att[t][4];
        }
    }
}

// ---------------- K0: tiny precomputes (one block, 256 threads) ----------------
__global__ void k0_precompute(const float* __restrict__ W_edge,
                              const float* __restrict__ att_edge,
                              const float* __restrict__ Wq2,
                              const float* __restrict__ bq2,
                              const float* __restrict__ ns,
                              const float* __restrict__ Wc,
                              const float* __restrict__ bc) {
    int t = threadIdx.x;
    {   // v[d][hd] = sum_c W_edge[d, hd*64+c] * att_edge[hd, c]
        int d = t >> 2, hd = t & 3;
        float s = 0.f;
        #pragma unroll 8
        for (int c = 0; c < 64; ++c)
            s += W_edge[d * HC + hd * 64 + c] * att_edge[hd * 64 + c];
        g_v[t] = s;
    }
    __syncthreads();
    if (t < Q_HID * HEADS) {
        int j = t >> 2, hd = t & 3;
        float s = 0.f;
        #pragma unroll 8
        for (int d = 0; d < 64; ++d)
            s += Wq2[j * 64 + d] * g_v[d * 4 + hd];
        g_wq2v[t] = s;
    }
    if (t >= 128 && t < 128 + HEADS) {
        int hd = t - 128;
        float s = 0.f;
        for (int d = 0; d < 64; ++d) s += bq2[d] * g_v[d * 4 + hd];
        g_bq2v[hd] = s;
    }
    if (t >= 192) {
        int j = t - 192;
        float s = bc[j];
        #pragma unroll
        for (int k = 0; k < 8; ++k) s += ns[k] * Wc[(64 + k) * 64 + j];
        g_t[j] = s;
    }
}

// ---------------- K2: FUSED edge pass (64 edges/block, 4 lanes/edge) ----------
// exp written to CSR-permuted slot; no den atomics (den computed in k4).
#define EPB 64
#define ROWF 80
__global__ __launch_bounds__(256) void k2_edge(const float* __restrict__ edge_attr,
                                               const float* __restrict__ pq,
                                               const float* __restrict__ Wq1,
                                               const float* __restrict__ bq1) {
    __shared__ float sa[EPB * ROWF];
    __shared__ float4 spq[EPB];
    __shared__ float4 sv[64];
    __shared__ float4 swq2v[Q_HID];
    __shared__ float  swq1[128], sbq1[Q_HID];

    int t = threadIdx.x;
    int e0 = blockIdx.x * EPB;

    if (t < 64)       sv[t]      = *(const float4*)&g_v[t * 4];
    else if (t < 96)  swq2v[t - 64] = *(const float4*)&g_wq2v[(t - 64) * 4];
    else if (t < 224) swq1[t - 96]  = Wq1[t - 96];
    else              sbq1[t - 224] = bq1[t - 224];

    {
        const float4* src = (const float4*)&edge_attr[(long long)e0 * 64];
        #pragma unroll
        for (int k = 0; k < 4; ++k) {
            int idx = t + k * 256;           // [0, 1024)
            int row = idx >> 4, col = idx & 15;
            float4 vv = __ldcs(&src[idx]);
            *(float4*)&sa[row * ROWF + col * 4] = vv;
        }
    }
    if (t < EPB) spq[t] = __ldcs(&((const float4*)pq)[e0 + t]);
    __syncthreads();

    int g = t >> 2;
    int i = t & 3;
    float p0 = 0.f, p1 = 0.f, p2 = 0.f, p3 = 0.f;

    #pragma unroll
    for (int j = 0; j < 4; ++j) {
        int col = i + j * 4;
        float4 a = *(const float4*)&sa[g * ROWF + col * 4];
        int d = col * 4;
        float4 v0 = sv[d], v1 = sv[d + 1], v2 = sv[d + 2], v3 = sv[d + 3];
        p0 += a.x * v0.x + a.y * v1.x + a.z * v2.x + a.w * v3.x;
        p1 += a.x * v0.y + a.y * v1.y + a.z * v2.y + a.w * v3.y;
        p2 += a.x * v0.z + a.y * v1.z + a.z * v2.z + a.w * v3.z;
        p3 += a.x * v0.w + a.y * v1.w + a.z * v2.w + a.w * v3.w;
    }
    {
        float4 q = spq[g];
        float q0 = q.x * 0.01f, q1 = q.y * 0.01f, q2 = q.z * 100.f, q3 = q.w * 100.f;
        #pragma unroll
        for (int uu = 0; uu < 8; ++uu) {
            int u = i * 8 + uu;
            float hj = q0 * swq1[u] + q1 * swq1[32 + u]
                     + q2 * swq1[64 + u] + q3 * swq1[96 + u] + sbq1[u];
            hj = fmaxf(hj, 0.f);
            float4 w = swq2v[u];
            p0 += hj * w.x; p1 += hj * w.y; p2 += hj * w.z; p3 += hj * w.w;
        }
    }
    #pragma unroll
    for (int o = 1; o < 4; o <<= 1) {
        p0 += __shfl_xor_sync(0xffffffffu, p0, o);
        p1 += __shfl_xor_sync(0xffffffffu, p1, o);
        p2 += __shfl_xor_sync(0xffffffffu, p2, o);
        p3 += __shfl_xor_sync(0xffffffffu, p3, o);
    }
    if (i == 0) {
        int e = e0 + g;
        int src = g_src[e];
        int dst = g_dst[e];
        float4 as = *(const float4*)&g_asrc[src * 4];
        float4 ad = *(const float4*)&g_adst[dst * 4];
        float4 bb = *(const float4*)&g_bq2v[0];
        float a0 = p0 + as.x + ad.x + bb.x;
        float a1 = p1 + as.y + ad.y + bb.y;
        float a2 = p2 + as.z + ad.z + bb.z;
        float a3 = p3 + as.w + ad.w + bb.w;
        a0 = (a0 > 0.f) ? a0 : NEG_SLOPE * a0;
        a1 = (a1 > 0.f) ? a1 : NEG_SLOPE * a1;
        a2 = (a2 > 0.f) ? a2 : NEG_SLOPE * a2;
        a3 = (a3 > 0.f) ? a3 : NEG_SLOPE * a3;
        float4 ex = make_float4(expf(a0), expf(a1), expf(a2), expf(a3));
        int pos = g_epos[e];
        *(float4*)&g_exp[pos * 4] = ex;   // CSR-permuted; max-shift omitted: same softmax
    }
}

// ---------------- K4: CSR pull (warp per dst, no atomics, den in-register) ----
__global__ void k4_pull() {
    int warp = (blockIdx.x * blockDim.x + threadIdx.x) >> 5;
    int lane = threadIdx.x & 31;
    if (warp >= N_NODES) return;
    int beg = __ldg(&g_rowptr[warp]), end = __ldg(&g_rowptr[warp + 1]);

    float a0x = 0.f, a0y = 0.f, a1x = 0.f, a1y = 0.f;
    float a2x = 0.f, a2y = 0.f, a3x = 0.f, a3y = 0.f;
    float d0 = 0.f, d1 = 0.f, d2 = 0.f, d3 = 0.f;

    for (int base = beg; base < end; base += 32) {
        int n = end - base; if (n > 32) n = 32;
        int srcL = 0;
        float exx = 0.f, exy = 0.f, exz = 0.f, exw = 0.f;
        if (base + lane < end) {
            srcL = __ldg(&g_cs[base + lane]);              // sequential
            float4 e4 = *(const float4*)&g_exp[(base + lane) * 4];  // sequential
            exx = e4.x; exy = e4.y; exz = e4.z; exw = e4.w;
        }
        for (int j = 0; j < n; ++j) {
            int   s  = __shfl_sync(0xffffffffu, srcL, j);
            float e0 = __shfl_sync(0xffffffffu, exx, j);
            float e1 = __shfl_sync(0xffffffffu, exy, j);
            float e2 = __shfl_sync(0xffffffffu, exz, j);
            float e3 = __shfl_sync(0xffffffffu, exw, j);
            d0 += e0; d1 += e1; d2 += e2; d3 += e3;
            const __half2* hb = (const __half2*)&g_hh[s * HC];
            float2 h0 = __half22float2(hb[lane]);         // head 0, ch 2l,2l+1
            float2 h1 = __half22float2(hb[32 + lane]);
            float2 h2 = __half22float2(hb[64 + lane]);
            float2 h3 = __half22float2(hb[96 + lane]);
            a0x += e0 * h0.x; a0y += e0 * h0.y;
            a1x += e1 * h1.x; a1y += e1 * h1.y;
            a2x += e2 * h2.x; a2y += e2 * h2.y;
            a3x += e3 * h3.x; a3y += e3 * h3.y;
        }
    }
    float r0 = (d0 > 0.f) ? 0.25f / d0 : 0.f;
    float r1 = (d1 > 0.f) ? 0.25f / d1 : 0.f;
    float r2 = (d2 > 0.f) ? 0.25f / d2 : 0.f;
    float r3 = (d3 > 0.f) ? 0.25f / d3 : 0.f;
    float2 o;
    o.x = a0x * r0 + a1x * r1 + a2x * r2 + a3x * r3;
    o.y = a0y * r0 + a1y * r1 + a2y * r2 + a3y * r3;
    *(float2*)&g_acc[warp * OUT_DIM + lane * 2] = o;
}

// ---------------- K5: out = relu(x_conv @ Wc[:64] + t)  (4 nodes/block) -------
__global__ void k5_out(const float* __restrict__ Wc,
                       const float* __restrict__ bias,
                       float* __restrict__ out) {
    __shared__ float xc[4][OUT_DIM];
    int t = threadIdx.x;
    int nl = t >> 6, j = t & 63;
    int n = blockIdx.x * 4 + nl;
    xc[nl][j] = g_acc[n * OUT_DIM + j] + bias[j];
    __syncthreads();
    float s = g_t[j];
    #pragma unroll 8
    for (int c = 0; c < OUT_DIM; ++c)
        s += xc[nl][c] * Wc[c * 64 + j];
    out[n * OUT_DIM + j] = fmaxf(s, 0.f);
}

// ---------------- launch ----------------
extern "C" void kernel_launch(void* const* d_in, const int* in_sizes, int n_in,
                              void* d_out, int out_size) {
    const float* x         = (const float*)d_in[0];
    const void*  ei        = d_in[1];
    const float* edge_attr = (const float*)d_in[2];
    const float* pq        = (const float*)d_in[3];
    const float* ns        = (const float*)d_in[4];
    const float* W         = (const float*)d_in[5];
    const float* att_src   = (const float*)d_in[6];
    const float* att_dst   = (const float*)d_in[7];
    const float* W_edge    = (const float*)d_in[8];
    const float* att_edge  = (const float*)d_in[9];
    const float* bias      = (const float*)d_in[10];
    const float* Wq1       = (const float*)d_in[11];
    const float* bq1       = (const float*)d_in[12];
    const float* Wq2       = (const float*)d_in[13];
    const float* bq2       = (const float*)d_in[14];
    const float* Wc        = (const float*)d_in[15];
    const float* bc        = (const float*)d_in[16];
    float* out = (float*)d_out;

    k_convert<<<(E_EDGES + 255) / 256, 256>>>(ei);                      // idx 0
    k_wcvt<<<(8 * 256 * 16 + 255) / 256, 256>>>(W);                     // idx 1
    k_xcvt<<<(N_NODES * IN_DIM / 8 + 255) / 256, 256>>>(x);             // idx 2
    k1_mma<<<(N_NODES + 63) / 64, 256>>>(att_src, att_dst);             // idx 3 (profiled)
    k_hist<<<(E_EDGES + 255) / 256, 256>>>();                           // idx 4
    k_scan<<<1, 1024>>>();                                              // idx 5
    k_scatter<<<(E_EDGES + 255) / 256, 256>>>();                        // idx 6
    k0_precompute<<<1, 256>>>(W_edge, att_edge, Wq2, bq2, ns, Wc, bc);  // idx 7
    k2_edge<<<E_EDGES / EPB, 256>>>(edge_attr, pq, Wq1, bq1);           // idx 8
    k4_pull<<<(N_NODES * 32 + 255) / 256, 256>>>();                     // idx 9
    k5_out<<<N_NODES / 4, 256>>>(Wc, bias, out);                        // idx 10
}

// round 14
// speedup vs baseline: 1.3240x; 1.3240x over previous
#include <cuda_runtime.h>
#include <cuda_fp16.h>
#include <cstdint>

#define N_NODES 50000
#define E_EDGES 800000
#define IN_DIM  128
#define OUT_DIM 64
#define HEADS   4
#define HC      256      // HEADS*OUT_DIM
#define Q_HID   32
#define NEG_SLOPE 0.2f

// ---------------- scratch (static device memory; no allocations) ----------------
__device__ __align__(16) __half g_hh[N_NODES * HC];     // 25.6 MB  h = x@W (fp16)
__device__ __align__(16) __half g_xh[N_NODES * IN_DIM]; // 12.8 MB  x in fp16
__device__ __align__(16) __half g_whT2[8 * 256 * 16];   // W^T fp16, chunked
__device__ __align__(16) float g_asrc[N_NODES * HEADS];
__device__ __align__(16) float g_adst[N_NODES * HEADS];
__device__ __align__(16) float g_ex[E_EDGES * HEADS];   // exp(alpha)
__device__ __align__(16) float g_den[N_NODES * HEADS];  // den, then 0.25/den
__device__ __align__(16) float g_acc[N_NODES * OUT_DIM];
__device__ __align__(16) float g_v[64 * HEADS];
__device__ __align__(16) float g_wq2v[Q_HID * HEADS];
__device__ __align__(16) float g_bq2v[HEADS];
__device__ float g_t[OUT_DIM];
__device__ int   g_is64;

// ---------------- K_wcvt_pre: W->fp16 (blocks 0-127) + k0 precompute (block 128)
__global__ void k_wcvt_pre(const float* __restrict__ W,
                           const float* __restrict__ W_edge,
                           const float* __restrict__ att_edge,
                           const float* __restrict__ Wq2,
                           const float* __restrict__ bq2,
                           const float* __restrict__ ns,
                           const float* __restrict__ Wc,
                           const float* __restrict__ bc,
                           const void* __restrict__ ei) {
    if (blockIdx.x < 128) {
        int i = blockIdx.x * 256 + threadIdx.x;     // [0, 32768)
        int kc = i >> 12, r = i & 4095;
        int n = r >> 4, ki = r & 15;
        g_whT2[i] = __float2half_rn(W[(kc * 16 + ki) * HC + n]);
        return;
    }
    // ---- block 128: dtype detect + tiny precomputes ----
    int t = threadIdx.x;
    if (t == 0) {
        // int64 values < 2^31 -> odd 32-bit words zero; int32 data -> random ids
        const int* p = (const int*)ei;
        int zeros = 0;
        for (int i = 1; i < 256; i += 2) zeros += (p[i] == 0);
        g_is64 = (zeros > 64);
    }
    {   // v[d][hd] = sum_c W_edge[d, hd*64+c] * att_edge[hd, c]
        int d = t >> 2, hd = t & 3;
        float s = 0.f;
        #pragma unroll 8
        for (int c = 0; c < 64; ++c)
            s += W_edge[d * HC + hd * 64 + c] * att_edge[hd * 64 + c];
        g_v[t] = s;
    }
    __syncthreads();
    if (t < Q_HID * HEADS) {   // Wq2v[j][hd] = sum_d Wq2[j,d] * v[d][hd]
        int j = t >> 2, hd = t & 3;
        float s = 0.f;
        #pragma unroll 8
        for (int d = 0; d < 64; ++d)
            s += Wq2[j * 64 + d] * g_v[d * 4 + hd];
        g_wq2v[t] = s;
    }
    if (t >= 128 && t < 128 + HEADS) {
        int hd = t - 128;
        float s = 0.f;
        for (int d = 0; d < 64; ++d) s += bq2[d] * g_v[d * 4 + hd];
        g_bq2v[hd] = s;
    }
    if (t >= 192) {            // t[j] = bc[j] + sum_k ns[k]*Wc[64+k, j]
        int j = t - 192;
        float s = bc[j];
        #pragma unroll
        for (int k = 0; k < 8; ++k) s += ns[k] * Wc[(64 + k) * 64 + j];
        g_t[j] = s;
    }
}

// ---------------- K_xcvt: x -> fp16 + zero g_acc/g_den (800K threads) ---------
__global__ void k_xcvt(const float* __restrict__ x) {
    int i = blockIdx.x * blockDim.x + threadIdx.x;
    if (i >= N_NODES * IN_DIM / 8) return;           // 800000
    *(float4*)&g_acc[i * 4] = make_float4(0.f, 0.f, 0.f, 0.f);  // covers 3.2M
    if (i < N_NODES * HEADS) g_den[i] = 0.f;
    const float4* xp = (const float4*)x;
    float4 a = __ldcs(&xp[i * 2]);
    float4 b = __ldcs(&xp[i * 2 + 1]);
    __half2 h0 = __floats2half2_rn(a.x, a.y), h1 = __floats2half2_rn(a.z, a.w);
    __half2 h2 = __floats2half2_rn(b.x, b.y), h3 = __floats2half2_rn(b.z, b.w);
    uint4 u;
    u.x = *(uint32_t*)&h0; u.y = *(uint32_t*)&h1;
    u.z = *(uint32_t*)&h2; u.w = *(uint32_t*)&h3;
    *(uint4*)&g_xh[i * 8] = u;
}

// ---------------- K1: tensor-core GEMM + fused EXACT fp32 attention logits ----
__device__ __forceinline__ void mma16816(float* c, const uint32_t* a,
                                         uint32_t b0, uint32_t b1) {
    asm volatile(
        "mma.sync.aligned.m16n8k16.row.col.f32.f16.f16.f32 "
        "{%0,%1,%2,%3}, {%4,%5,%6,%7}, {%8,%9}, {%0,%1,%2,%3};\n"
        : "+f"(c[0]), "+f"(c[1]), "+f"(c[2]), "+f"(c[3])
        : "r"(a[0]), "r"(a[1]), "r"(a[2]), "r"(a[3]), "r"(b0), "r"(b1));
}

__global__ __launch_bounds__(256) void k1_mma(const float* __restrict__ att_src,
                                              const float* __restrict__ att_dst) {
    __shared__ __half as[64][136];   // A tile, padded
    __shared__ __half ws[256][24];   // W chunk [n][k16], padded
    __shared__ float s_att[64][8];   // [row][head: src 0-3 | dst 4-7]
    int t = threadIdx.x, lane = t & 31, w = t >> 5;
    int wm = w & 1, wn = w >> 1;     // wn == head (64-col span)
    int g = lane >> 2, tg = lane & 3;
    int blk = blockIdx.x;

    {   // stage A tile (64 rows x 128 halves)
        int r = t >> 2, part = t & 3;
        int node = blk * 64 + r;
        uint4 z = make_uint4(0, 0, 0, 0);
        uint4* dst = (uint4*)&as[r][part * 32];
        if (node < N_NODES) {
            const uint4* srcp = (const uint4*)&g_xh[node * IN_DIM + part * 32];
            dst[0] = srcp[0]; dst[1] = srcp[1]; dst[2] = srcp[2]; dst[3] = srcp[3];
        } else {
            dst[0] = z; dst[1] = z; dst[2] = z; dst[3] = z;
        }
    }

    float acc[2][8][4];
    #pragma unroll
    for (int mt = 0; mt < 2; ++mt)
        #pragma unroll
        for (int nt = 0; nt < 8; ++nt)
            #pragma unroll
            for (int i = 0; i < 4; ++i) acc[mt][nt][i] = 0.f;

    for (int kc = 0; kc < 8; ++kc) {
        __syncthreads();
        {   // stage W chunk (8KB contiguous, coalesced)
            const uint4* srcp = (const uint4*)&g_whT2[kc * 4096];
            uint4 w0 = srcp[t * 2], w1 = srcp[t * 2 + 1];
            *(uint4*)&ws[t][0] = w0;
            *(uint4*)&ws[t][8] = w1;
        }
        __syncthreads();
        uint32_t a[2][4];
        #pragma unroll
        for (int mt = 0; mt < 2; ++mt) {
            int r = wm * 32 + mt * 16 + g;
            int kb = kc * 16 + tg * 2;
            a[mt][0] = *(const uint32_t*)&as[r][kb];
            a[mt][1] = *(const uint32_t*)&as[r + 8][kb];
            a[mt][2] = *(const uint32_t*)&as[r][kb + 8];
            a[mt][3] = *(const uint32_t*)&as[r + 8][kb + 8];
        }
        #pragma unroll
        for (int nt = 0; nt < 8; ++nt) {
            int n = wn * 64 + nt * 8 + g;
            uint32_t b0 = *(const uint32_t*)&ws[n][tg * 2];
            uint32_t b1 = *(const uint32_t*)&ws[n][tg * 2 + 8];
            mma16816(acc[0][nt], a[0], b0, b1);
            mma16816(acc[1][nt], a[1], b0, b1);
        }
    }

    // ---- fp16 store of h ----
    #pragma unroll
    for (int mt = 0; mt < 2; ++mt) {
        int r = blk * 64 + wm * 32 + mt * 16 + g;
        #pragma unroll
        for (int nt = 0; nt < 8; ++nt) {
            int col = wn * 64 + nt * 8 + tg * 2;
            if (r < N_NODES) {
                __half2 h01 = __floats2half2_rn(acc[mt][nt][0], acc[mt][nt][1]);
                *(uint32_t*)&g_hh[r * HC + col] = *(uint32_t*)&h01;
            }
            if (r + 8 < N_NODES) {
                __half2 h23 = __floats2half2_rn(acc[mt][nt][2], acc[mt][nt][3]);
                *(uint32_t*)&g_hh[(r + 8) * HC + col] = *(uint32_t*)&h23;
            }
        }
    }

    // ---- exact fp32 attention logits from the accumulators ----
    float2 asv[8], adv[8];
    #pragma unroll
    for (int nt = 0; nt < 8; ++nt) {
        int col = wn * 64 + nt * 8 + tg * 2;
        asv[nt] = *(const float2*)&att_src[col];
        adv[nt] = *(const float2*)&att_dst[col];
    }
    #pragma unroll
    for (int mt = 0; mt < 2; ++mt) {
        #pragma unroll
        for (int half = 0; half < 2; ++half) {
            float ps = 0.f, pd = 0.f;
            #pragma unroll
            for (int nt = 0; nt < 8; ++nt) {
                float c0 = acc[mt][nt][half * 2], c1 = acc[mt][nt][half * 2 + 1];
                ps += c0 * asv[nt].x + c1 * asv[nt].y;
                pd += c0 * adv[nt].x + c1 * adv[nt].y;
            }
            ps += __shfl_xor_sync(0xffffffffu, ps, 1);
            ps += __shfl_xor_sync(0xffffffffu, ps, 2);
            pd += __shfl_xor_sync(0xffffffffu, pd, 1);
            pd += __shfl_xor_sync(0xffffffffu, pd, 2);
            if (tg == 0) {
                int rl = wm * 32 + mt * 16 + g + half * 8;
                s_att[rl][wn] = ps;
                s_att[rl][4 + wn] = pd;
            }
        }
    }
    __syncthreads();
    if (t < 64) {
        int node = blk * 64 + t;
        if (node < N_NODES) {
            *(float4*)&g_asrc[node * 4] = *(const float4*)&s_att[t][0];
            *(float4*)&g_adst[node * 4] = *(const float4*)&s_att[t][4];
        }
    }
}

// ---------------- K2: FUSED edge pass (64 edges/block, 4 lanes/edge) ----------
// Reads edge_index directly (runtime dtype). Writes g_ex + den float4 atomics.
#define EPB 64
#define ROWF 80
__global__ __launch_bounds__(256) void k2_edge(const void* __restrict__ ei,
                                               const float* __restrict__ edge_attr,
                                               const float* __restrict__ pq,
                                               const float* __restrict__ Wq1,
                                               const float* __restrict__ bq1) {
    __shared__ float sa[EPB * ROWF];
    __shared__ float4 spq[EPB];
    __shared__ float4 sv[64];
    __shared__ float4 swq2v[Q_HID];
    __shared__ float  swq1[128], sbq1[Q_HID];

    int t = threadIdx.x;
    int e0 = blockIdx.x * EPB;

    if (t < 64)       sv[t]      = *(const float4*)&g_v[t * 4];
    else if (t < 96)  swq2v[t - 64] = *(const float4*)&g_wq2v[(t - 64) * 4];
    else if (t < 224) swq1[t - 96]  = Wq1[t - 96];
    else              sbq1[t - 224] = bq1[t - 224];

    {
        const float4* src = (const float4*)&edge_attr[(long long)e0 * 64];
        #pragma unroll
        for (int k = 0; k < 4; ++k) {
            int idx = t + k * 256;           // [0, 1024)
            int row = idx >> 4, col = idx & 15;
            float4 vv = __ldcs(&src[idx]);
            *(float4*)&sa[row * ROWF + col * 4] = vv;
        }
    }
    if (t < EPB) spq[t] = __ldcs(&((const float4*)pq)[e0 + t]);
    __syncthreads();

    int g = t >> 2;
    int i = t & 3;
    float p0 = 0.f, p1 = 0.f, p2 = 0.f, p3 = 0.f;

    #pragma unroll
    for (int j = 0; j < 4; ++j) {
        int col = i + j * 4;
        float4 a = *(const float4*)&sa[g * ROWF + col * 4];
        int d = col * 4;
        float4 v0 = sv[d], v1 = sv[d + 1], v2 = sv[d + 2], v3 = sv[d + 3];
        p0 += a.x * v0.x + a.y * v1.x + a.z * v2.x + a.w * v3.x;
        p1 += a.x * v0.y + a.y * v1.y + a.z * v2.y + a.w * v3.y;
        p2 += a.x * v0.z + a.y * v1.z + a.z * v2.z + a.w * v3.z;
        p3 += a.x * v0.w + a.y * v1.w + a.z * v2.w + a.w * v3.w;
    }
    {
        float4 q = spq[g];
        float q0 = q.x * 0.01f, q1 = q.y * 0.01f, q2 = q.z * 100.f, q3 = q.w * 100.f;
        #pragma unroll
        for (int uu = 0; uu < 8; ++uu) {
            int u = i * 8 + uu;
            float hj = q0 * swq1[u] + q1 * swq1[32 + u]
                     + q2 * swq1[64 + u] + q3 * swq1[96 + u] + sbq1[u];
            hj = fmaxf(hj, 0.f);
            float4 w = swq2v[u];
            p0 += hj * w.x; p1 += hj * w.y; p2 += hj * w.z; p3 += hj * w.w;
        }
    }
    #pragma unroll
    for (int o = 1; o < 4; o <<= 1) {
        p0 += __shfl_xor_sync(0xffffffffu, p0, o);
        p1 += __shfl_xor_sync(0xffffffffu, p1, o);
        p2 += __shfl_xor_sync(0xffffffffu, p2, o);
        p3 += __shfl_xor_sync(0xffffffffu, p3, o);
    }
    if (i == 0) {
        int e = e0 + g;
        int src, dst;
        if (g_is64) {
            const long long* p = (const long long*)ei;
            src = (int)__ldg(&p[e]);
            dst = (int)__ldg(&p[E_EDGES + e]);
        } else {
            const int* p = (const int*)ei;
            src = __ldg(&p[e]);
            dst = __ldg(&p[E_EDGES + e]);
        }
        float4 as = *(const float4*)&g_asrc[src * 4];
        float4 ad = *(const float4*)&g_adst[dst * 4];
        float4 bb = *(const float4*)&g_bq2v[0];
        float a0 = p0 + as.x + ad.x + bb.x;
        float a1 = p1 + as.y + ad.y + bb.y;
        float a2 = p2 + as.z + ad.z + bb.z;
        float a3 = p3 + as.w + ad.w + bb.w;
        a0 = (a0 > 0.f) ? a0 : NEG_SLOPE * a0;
        a1 = (a1 > 0.f) ? a1 : NEG_SLOPE * a1;
        a2 = (a2 > 0.f) ? a2 : NEG_SLOPE * a2;
        a3 = (a3 > 0.f) ? a3 : NEG_SLOPE * a3;
        float4 ex = make_float4(expf(a0), expf(a1), expf(a2), expf(a3));
        *(float4*)&g_ex[e * 4] = ex;          // max-shift omitted: identical softmax
        atomicAdd((float4*)&g_den[dst * 4], ex);
    }
}

// ---------------- K3: den -> 0.25/den (head-mean folded) ----------------------
__global__ void k3_invden() {
    int i = blockIdx.x * blockDim.x + threadIdx.x;
    if (i >= N_NODES * HEADS) return;
    float d = g_den[i];
    g_den[i] = (d > 0.f) ? 0.25f / d : 0.f;
}

// ---------------- K4: aggregate (HALF-warp per edge, float4 atomics) ----------
__global__ void k4_aggregate(const void* __restrict__ ei) {
    int gid = blockIdx.x * blockDim.x + threadIdx.x;
    int e = gid >> 4;              // half-warp per edge
    if (e >= E_EDGES) return;
    int l = gid & 15;
    int src, dst;
    if (g_is64) {
        const long long* p = (const long long*)ei;
        src = (int)__ldg(&p[e]);
        dst = (int)__ldg(&p[E_EDGES + e]);
    } else {
        const int* p = (const int*)ei;
        src = __ldg(&p[e]);
        dst = __ldg(&p[E_EDGES + e]);
    }

    float4 ex  = *(const float4*)&g_ex[e * 4];
    float4 inv = *(const float4*)&g_den[dst * 4];
    float w0 = ex.x * inv.x;
    float w1 = ex.y * inv.y;
    float w2 = ex.z * inv.z;
    float w3 = ex.w * inv.w;

    int c0 = l * 4;                // 4 channels per lane
    const __half* hb = &g_hh[src * HC];
    uint2 u0 = *(const uint2*)&hb[c0];
    uint2 u1 = *(const uint2*)&hb[64 + c0];
    uint2 u2 = *(const uint2*)&hb[128 + c0];
    uint2 u3 = *(const uint2*)&hb[192 + c0];
    float2 a0 = __half22float2(*(__half2*)&u0.x), b0 = __half22float2(*(__half2*)&u0.y);
    float2 a1 = __half22float2(*(__half2*)&u1.x), b1 = __half22float2(*(__half2*)&u1.y);
    float2 a2 = __half22float2(*(__half2*)&u2.x), b2 = __half22float2(*(__half2*)&u2.y);
    float2 a3 = __half22float2(*(__half2*)&u3.x), b3 = __half22float2(*(__half2*)&u3.y);

    float4 m;
    m.x = w0 * a0.x + w1 * a1.x + w2 * a2.x + w3 * a3.x;
    m.y = w0 * a0.y + w1 * a1.y + w2 * a2.y + w3 * a3.y;
    m.z = w0 * b0.x + w1 * b1.x + w2 * b2.x + w3 * b3.x;
    m.w = w0 * b0.y + w1 * b1.y + w2 * b2.y + w3 * b3.y;
    atomicAdd((float4*)&g_acc[dst * OUT_DIM + c0], m);
}

// ---------------- K5: out = relu(x_conv @ Wc[:64] + t)  (4 nodes/block) -------
__global__ void k5_out(const float* __restrict__ Wc,
                       const float* __restrict__ bias,
                       float* __restrict__ out) {
    __shared__ float xc[4][OUT_DIM];
    int t = threadIdx.x;
    int nl = t >> 6, j = t & 63;
    int n = blockIdx.x * 4 + nl;
    xc[nl][j] = g_acc[n * OUT_DIM + j] + bias[j];
    __syncthreads();
    float s = g_t[j];
    #pragma unroll 8
    for (int c = 0; c < OUT_DIM; ++c)
        s += xc[nl][c] * Wc[c * 64 + j];
    out[n * OUT_DIM + j] = fmaxf(s, 0.f);
}

// ---------------- launch ----------------
extern "C" void kernel_launch(void* const* d_in, const int* in_sizes, int n_in,
                              void* d_out, int out_size) {
    const float* x         = (const float*)d_in[0];
    const void*  ei        = d_in[1];
    const float* edge_attr = (const float*)d_in[2];
    const float* pq        = (const float*)d_in[3];
    const float* ns        = (const float*)d_in[4];
    const float* W         = (const float*)d_in[5];
    const float* att_src   = (const float*)d_in[6];
    const float* att_dst   = (const float*)d_in[7];
    const float* W_edge    = (const float*)d_in[8];
    const float* att_edge  = (const float*)d_in[9];
    const float* bias      = (const float*)d_in[10];
    const float* Wq1       = (const float*)d_in[11];
    const float* bq1       = (const float*)d_in[12];
    const float* Wq2       = (const float*)d_in[13];
    const float* bq2       = (const float*)d_in[14];
    const float* Wc        = (const float*)d_in[15];
    const float* bc        = (const float*)d_in[16];
    float* out = (float*)d_out;

    k_wcvt_pre<<<129, 256>>>(W, W_edge, att_edge, Wq2, bq2, ns, Wc, bc, ei); // idx 0
    k_xcvt<<<(N_NODES * IN_DIM / 8 + 255) / 256, 256>>>(x);                  // idx 1
    k1_mma<<<(N_NODES + 63) / 64, 256>>>(att_src, att_dst);                  // idx 2
    k2_edge<<<E_EDGES / EPB, 256>>>(ei, edge_attr, pq, Wq1, bq1);            // idx 3 (profiled)
    k3_invden<<<(N_NODES * HEADS + 255) / 256, 256>>>();                     // idx 4
    k4_aggregate<<<(E_EDGES * 16 + 255) / 256, 256>>>(ei);                   // idx 5
    k5_out<<<N_NODES / 4, 256>>>(Wc, bias, out);                             // idx 6
}

// round 15
// speedup vs baseline: 1.4999x; 1.1329x over previous
#include <cuda_runtime.h>
#include <cuda_fp16.h>
#include <cstdint>

#define N_NODES 50000
#define E_EDGES 800000
#define IN_DIM  128
#define OUT_DIM 64
#define HEADS   4
#define HC      256      // HEADS*OUT_DIM
#define Q_HID   32
#define NEG_SLOPE 0.2f

// ---------------- scratch (static device memory; no allocations) ----------------
__device__ __align__(16) __half g_hh[N_NODES * HC];     // 25.6 MB  h = x@W (fp16)
__device__ __align__(16) __half g_xh[N_NODES * IN_DIM]; // 12.8 MB  x in fp16
__device__ __align__(16) __half g_whT2[8 * 256 * 16];   // W^T fp16, chunked
__device__ __align__(16) float g_asrc[N_NODES * HEADS];
__device__ __align__(16) float g_adst[N_NODES * HEADS];
__device__ __align__(16) float g_ex[E_EDGES * HEADS];   // exp(alpha)
__device__ __align__(16) float g_den[N_NODES * HEADS];  // den, then 0.25/den
__device__ __align__(16) float g_acc[N_NODES * OUT_DIM];
__device__ __align__(16) float g_v[64 * HEADS];
__device__ __align__(16) float g_wq2v[Q_HID * HEADS];
__device__ __align__(16) float g_mlp[4 * 34 * 4];       // per-sublane MLP blob (float4[4][34])
__device__ __align__(16) float g_bq2v[HEADS];
__device__ float g_t[OUT_DIM];
__device__ int   g_is64;

// ---------------- K_wcvt_pre: W->fp16 (blocks 0-127) + precompute (block 128) --
__global__ void k_wcvt_pre(const float* __restrict__ W,
                           const float* __restrict__ W_edge,
                           const float* __restrict__ att_edge,
                           const float* __restrict__ Wq1,
                           const float* __restrict__ bq1,
                           const float* __restrict__ Wq2,
                           const float* __restrict__ bq2,
                           const float* __restrict__ ns,
                           const float* __restrict__ Wc,
                           const float* __restrict__ bc,
                           const void* __restrict__ ei) {
    if (blockIdx.x < 128) {
        int i = blockIdx.x * 256 + threadIdx.x;     // [0, 32768)
        int kc = i >> 12, r = i & 4095;
        int n = r >> 4, ki = r & 15;
        g_whT2[i] = __float2half_rn(W[(kc * 16 + ki) * HC + n]);
        return;
    }
    // ---- block 128: dtype detect + tiny precomputes ----
    int t = threadIdx.x;
    if (t == 0) {
        const int* p = (const int*)ei;
        int zeros = 0;
        for (int i = 1; i < 256; i += 2) zeros += (p[i] == 0);
        g_is64 = (zeros > 64);
    }
    {   // v[d][hd] = sum_c W_edge[d, hd*64+c] * att_edge[hd, c]
        int d = t >> 2, hd = t & 3;
        float s = 0.f;
        #pragma unroll 8
        for (int c = 0; c < 64; ++c)
            s += W_edge[d * HC + hd * 64 + c] * att_edge[hd * 64 + c];
        g_v[t] = s;
    }
    __syncthreads();
    if (t < Q_HID * HEADS) {   // Wq2v[j][hd] = sum_d Wq2[j,d] * v[d][hd]
        int j = t >> 2, hd = t & 3;
        float s = 0.f;
        #pragma unroll 8
        for (int d = 0; d < 64; ++d)
            s += Wq2[j * 64 + d] * g_v[d * 4 + hd];
        g_wq2v[t] = s;
    }
    if (t >= 128 && t < 128 + HEADS) {
        int hd = t - 128;
        float s = 0.f;
        for (int d = 0; d < 64; ++d) s += bq2[d] * g_v[d * 4 + hd];
        g_bq2v[hd] = s;
    }
    if (t >= 192) {            // t[j] = bc[j] + sum_k ns[k]*Wc[64+k, j]
        int j = t - 192;
        float s = bc[j];
        #pragma unroll
        for (int k = 0; k < 8; ++k) s += ns[k] * Wc[(64 + k) * 64 + j];
        g_t[j] = s;
    }
    __syncthreads();
    // ---- MLP blob: [i][2u'] = wq1 4 cols of unit u=i*8+u'; [i][2u'+1] = wq2v[u];
    //      [i][32],[i][33] = biases (units i*8..i*8+3, i*8+4..i*8+7)
    if (t < 32) {   // one thread per hidden unit u
        int u = t, i = u >> 3, up = u & 7;
        float4 w1 = make_float4(Wq1[u], Wq1[32 + u], Wq1[64 + u], Wq1[96 + u]);
        *(float4*)&g_mlp[(i * 34 + 2 * up) * 4] = w1;
        *(float4*)&g_mlp[(i * 34 + 2 * up + 1) * 4] = *(const float4*)&g_wq2v[u * 4];
    } else if (t < 40) {  // biases: t-32 = i*2 + which
        int q = t - 32, i = q >> 1, which = q & 1;
        *(float4*)&g_mlp[(i * 34 + 32 + which) * 4] =
            *(const float4*)&bq1[i * 8 + which * 4];
    }
}

// ---------------- K_xcvt: x -> fp16 + zero g_acc/g_den (800K threads) ---------
__global__ void k_xcvt(const float* __restrict__ x) {
    int i = blockIdx.x * blockDim.x + threadIdx.x;
    if (i >= N_NODES * IN_DIM / 8) return;           // 800000
    *(float4*)&g_acc[i * 4] = make_float4(0.f, 0.f, 0.f, 0.f);  // covers 3.2M
    if (i < N_NODES * HEADS) g_den[i] = 0.f;
    const float4* xp = (const float4*)x;
    float4 a = __ldcs(&xp[i * 2]);
    float4 b = __ldcs(&xp[i * 2 + 1]);
    __half2 h0 = __floats2half2_rn(a.x, a.y), h1 = __floats2half2_rn(a.z, a.w);
    __half2 h2 = __floats2half2_rn(b.x, b.y), h3 = __floats2half2_rn(b.z, b.w);
    uint4 u;
    u.x = *(uint32_t*)&h0; u.y = *(uint32_t*)&h1;
    u.z = *(uint32_t*)&h2; u.w = *(uint32_t*)&h3;
    *(uint4*)&g_xh[i * 8] = u;
}

// ---------------- K1: tensor-core GEMM + fused EXACT fp32 attention logits ----
__device__ __forceinline__ void mma16816(float* c, const uint32_t* a,
                                         uint32_t b0, uint32_t b1) {
    asm volatile(
        "mma.sync.aligned.m16n8k16.row.col.f32.f16.f16.f32 "
        "{%0,%1,%2,%3}, {%4,%5,%6,%7}, {%8,%9}, {%0,%1,%2,%3};\n"
        : "+f"(c[0]), "+f"(c[1]), "+f"(c[2]), "+f"(c[3])
        : "r"(a[0]), "r"(a[1]), "r"(a[2]), "r"(a[3]), "r"(b0), "r"(b1));
}

__global__ __launch_bounds__(256) void k1_mma(const float* __restrict__ att_src,
                                              const float* __restrict__ att_dst) {
    __shared__ __half as[64][136];   // A tile, padded
    __shared__ __half ws[256][24];   // W chunk [n][k16], padded
    __shared__ float s_att[64][8];   // [row][head: src 0-3 | dst 4-7]
    int t = threadIdx.x, lane = t & 31, w = t >> 5;
    int wm = w & 1, wn = w >> 1;     // wn == head (64-col span)
    int g = lane >> 2, tg = lane & 3;
    int blk = blockIdx.x;

    {   // stage A tile (64 rows x 128 halves)
        int r = t >> 2, part = t & 3;
        int node = blk * 64 + r;
        uint4 z = make_uint4(0, 0, 0, 0);
        uint4* dst = (uint4*)&as[r][part * 32];
        if (node < N_NODES) {
            const uint4* srcp = (const uint4*)&g_xh[node * IN_DIM + part * 32];
            dst[0] = srcp[0]; dst[1] = srcp[1]; dst[2] = srcp[2]; dst[3] = srcp[3];
        } else {
            dst[0] = z; dst[1] = z; dst[2] = z; dst[3] = z;
        }
    }

    float acc[2][8][4];
    #pragma unroll
    for (int mt = 0; mt < 2; ++mt)
        #pragma unroll
        for (int nt = 0; nt < 8; ++nt)
            #pragma unroll
            for (int i = 0; i < 4; ++i) acc[mt][nt][i] = 0.f;

    for (int kc = 0; kc < 8; ++kc) {
        __syncthreads();
        {   // stage W chunk (8KB contiguous, coalesced)
            const uint4* srcp = (const uint4*)&g_whT2[kc * 4096];
            uint4 w0 = srcp[t * 2], w1 = srcp[t * 2 + 1];
            *(uint4*)&ws[t][0] = w0;
            *(uint4*)&ws[t][8] = w1;
        }
        __syncthreads();
        uint32_t a[2][4];
        #pragma unroll
        for (int mt = 0; mt < 2; ++mt) {
            int r = wm * 32 + mt * 16 + g;
            int kb = kc * 16 + tg * 2;
            a[mt][0] = *(const uint32_t*)&as[r][kb];
            a[mt][1] = *(const uint32_t*)&as[r + 8][kb];
            a[mt][2] = *(const uint32_t*)&as[r][kb + 8];
            a[mt][3] = *(const uint32_t*)&as[r + 8][kb + 8];
        }
        #pragma unroll
        for (int nt = 0; nt < 8; ++nt) {
            int n = wn * 64 + nt * 8 + g;
            uint32_t b0 = *(const uint32_t*)&ws[n][tg * 2];
            uint32_t b1 = *(const uint32_t*)&ws[n][tg * 2 + 8];
            mma16816(acc[0][nt], a[0], b0, b1);
            mma16816(acc[1][nt], a[1], b0, b1);
        }
    }

    // ---- fp16 store of h ----
    #pragma unroll
    for (int mt = 0; mt < 2; ++mt) {
        int r = blk * 64 + wm * 32 + mt * 16 + g;
        #pragma unroll
        for (int nt = 0; nt < 8; ++nt) {
            int col = wn * 64 + nt * 8 + tg * 2;
            if (r < N_NODES) {
                __half2 h01 = __floats2half2_rn(acc[mt][nt][0], acc[mt][nt][1]);
                *(uint32_t*)&g_hh[r * HC + col] = *(uint32_t*)&h01;
            }
            if (r + 8 < N_NODES) {
                __half2 h23 = __floats2half2_rn(acc[mt][nt][2], acc[mt][nt][3]);
                *(uint32_t*)&g_hh[(r + 8) * HC + col] = *(uint32_t*)&h23;
            }
        }
    }

    // ---- exact fp32 attention logits from the accumulators ----
    float2 asv[8], adv[8];
    #pragma unroll
    for (int nt = 0; nt < 8; ++nt) {
        int col = wn * 64 + nt * 8 + tg * 2;
        asv[nt] = *(const float2*)&att_src[col];
        adv[nt] = *(const float2*)&att_dst[col];
    }
    #pragma unroll
    for (int mt = 0; mt < 2; ++mt) {
        #pragma unroll
        for (int half = 0; half < 2; ++half) {
            float ps = 0.f, pd = 0.f;
            #pragma unroll
            for (int nt = 0; nt < 8; ++nt) {
                float c0 = acc[mt][nt][half * 2], c1 = acc[mt][nt][half * 2 + 1];
                ps += c0 * asv[nt].x + c1 * asv[nt].y;
                pd += c0 * adv[nt].x + c1 * adv[nt].y;
            }
            ps += __shfl_xor_sync(0xffffffffu, ps, 1);
            ps += __shfl_xor_sync(0xffffffffu, ps, 2);
            pd += __shfl_xor_sync(0xffffffffu, pd, 1);
            pd += __shfl_xor_sync(0xffffffffu, pd, 2);
            if (tg == 0) {
                int rl = wm * 32 + mt * 16 + g + half * 8;
                s_att[rl][wn] = ps;
                s_att[rl][4 + wn] = pd;
            }
        }
    }
    __syncthreads();
    if (t < 64) {
        int node = blk * 64 + t;
        if (node < N_NODES) {
            *(float4*)&g_asrc[node * 4] = *(const float4*)&s_att[t][0];
            *(float4*)&g_adst[node * 4] = *(const float4*)&s_att[t][4];
        }
    }
}

// ---------------- K2: FUSED edge pass (64 edges/block, 4 lanes/edge) ----------
// fp16 smem staging (halved STS/LDS slots), prepacked MLP blob, den atomics.
#define EPB 64
#define ROWH 72        // smem row stride in halves (64 data + 8 pad)
__global__ __launch_bounds__(256) void k2_edge(const void* __restrict__ ei,
                                               const float* __restrict__ edge_attr,
                                               const float* __restrict__ pq) {
    __shared__ __half sah[EPB * ROWH];     // 9.2 KB staged edge_attr (fp16)
    __shared__ float4 spq[EPB];            // path quality per edge
    __shared__ float4 sv[64];              // v table (fp32)
    __shared__ float4 s_mlp[4 * 34];       // per-sublane MLP blob

    int t = threadIdx.x;
    int e0 = blockIdx.x * EPB;

    // stage tables
    if (t < 64) {
        sv[t] = *(const float4*)&g_v[t * 4];
        spq[t] = __ldcs(&((const float4*)pq)[e0 + t]);
    } else if (t < 64 + 136) {
        s_mlp[t - 64] = *(const float4*)&g_mlp[(t - 64) * 4];
    }

    // stage edge_attr: 1024 float4 coalesced loads -> fp16 smem
    {
        const float4* src = (const float4*)&edge_attr[(long long)e0 * 64];
        #pragma unroll
        for (int k = 0; k < 4; ++k) {
            int idx = t + k * 256;           // [0, 1024)
            int row = idx >> 4, c = idx & 15;
            float4 vv = __ldcs(&src[idx]);
            __half2 lo = __floats2half2_rn(vv.x, vv.y);
            __half2 hi = __floats2half2_rn(vv.z, vv.w);
            uint2 u; u.x = *(uint32_t*)&lo; u.y = *(uint32_t*)&hi;
            *(uint2*)&sah[row * ROWH + c * 4] = u;   // 8B store, conflict-free
        }
    }
    __syncthreads();

    int g = t >> 2;          // edge within block [0,64)
    int i = t & 3;           // sub-lane [0,4)
    float p0 = 0.f, p1 = 0.f, p2 = 0.f, p3 = 0.f;

    // main dot: lane i covers float4-cols {i, i+4, i+8, i+12}
    #pragma unroll
    for (int j = 0; j < 4; ++j) {
        int col = i + j * 4;
        uint2 u = *(const uint2*)&sah[g * ROWH + col * 4];
        float2 f01 = __half22float2(*(__half2*)&u.x);
        float2 f23 = __half22float2(*(__half2*)&u.y);
        int d = col * 4;
        float4 v0 = sv[d], v1 = sv[d + 1], v2 = sv[d + 2], v3 = sv[d + 3];
        p0 += f01.x * v0.x + f01.y * v1.x + f23.x * v2.x + f23.y * v3.x;
        p1 += f01.x * v0.y + f01.y * v1.y + f23.x * v2.y + f23.y * v3.y;
        p2 += f01.x * v0.z + f01.y * v1.z + f23.x * v2.z + f23.y * v3.z;
        p3 += f01.x * v0.w + f01.y * v1.w + f23.x * v2.w + f23.y * v3.w;
    }
    // path-quality MLP via prepacked blob: lane i handles units [i*8, i*8+8)
    {
        float4 q = spq[g];
        float q0 = q.x * 0.01f, q1 = q.y * 0.01f, q2 = q.z * 100.f, q3 = q.w * 100.f;
        const float4* blob = &s_mlp[i * 34];
        float bias[8];
        *(float4*)&bias[0] = blob[32];
        *(float4*)&bias[4] = blob[33];
        #pragma unroll
        for (int uu = 0; uu < 8; ++uu) {
            float4 w1 = blob[2 * uu];
            float4 wv = blob[2 * uu + 1];
            float hj = q0 * w1.x + q1 * w1.y + q2 * w1.z + q3 * w1.w + bias[uu];
            hj = fmaxf(hj, 0.f);
            p0 += hj * wv.x; p1 += hj * wv.y; p2 += hj * wv.z; p3 += hj * wv.w;
        }
    }
    // reduce over the 4 sub-lanes
    #pragma unroll
    for (int o = 1; o < 4; o <<= 1) {
        p0 += __shfl_xor_sync(0xffffffffu, p0, o);
        p1 += __shfl_xor_sync(0xffffffffu, p1, o);
        p2 += __shfl_xor_sync(0xffffffffu, p2, o);
        p3 += __shfl_xor_sync(0xffffffffu, p3, o);
    }
    // leaders: finish alpha -> exp -> store + den atomic
    if (i == 0) {
        int e = e0 + g;
        int src, dst;
        if (g_is64) {
            const long long* p = (const long long*)ei;
            src = (int)__ldg(&p[e]);
            dst = (int)__ldg(&p[E_EDGES + e]);
        } else {
            const int* p = (const int*)ei;
            src = __ldg(&p[e]);
            dst = __ldg(&p[E_EDGES + e]);
        }
        float4 as = *(const float4*)&g_asrc[src * 4];
        float4 ad = *(const float4*)&g_adst[dst * 4];
        float4 bb = *(const float4*)&g_bq2v[0];
        float a0 = p0 + as.x + ad.x + bb.x;
        float a1 = p1 + as.y + ad.y + bb.y;
        float a2 = p2 + as.z + ad.z + bb.z;
        float a3 = p3 + as.w + ad.w + bb.w;
        a0 = (a0 > 0.f) ? a0 : NEG_SLOPE * a0;
        a1 = (a1 > 0.f) ? a1 : NEG_SLOPE * a1;
        a2 = (a2 > 0.f) ? a2 : NEG_SLOPE * a2;
        a3 = (a3 > 0.f) ? a3 : NEG_SLOPE * a3;
        float4 ex = make_float4(expf(a0), expf(a1), expf(a2), expf(a3));
        *(float4*)&g_ex[e * 4] = ex;          // max-shift omitted: identical softmax
        atomicAdd((float4*)&g_den[dst * 4], ex);
    }
}

// ---------------- K3: den -> 0.25/den (head-mean folded) ----------------------
__global__ void k3_invden() {
    int i = blockIdx.x * blockDim.x + threadIdx.x;
    if (i >= N_NODES * HEADS) return;
    float d = g_den[i];
    g_den[i] = (d > 0.f) ? 0.25f / d : 0.f;
}

// ---------------- K4: aggregate (HALF-warp per edge, float4 atomics) ----------
__global__ void k4_aggregate(const void* __restrict__ ei) {
    int gid = blockIdx.x * blockDim.x + threadIdx.x;
    int e = gid >> 4;              // half-warp per edge
    if (e >= E_EDGES) return;
    int l = gid & 15;
    int src, dst;
    if (g_is64) {
        const long long* p = (const long long*)ei;
        src = (int)__ldg(&p[e]);
        dst = (int)__ldg(&p[E_EDGES + e]);
    } else {
        const int* p = (const int*)ei;
        src = __ldg(&p[e]);
        dst = __ldg(&p[E_EDGES + e]);
    }

    float4 ex  = *(const float4*)&g_ex[e * 4];
    float4 inv = *(const float4*)&g_den[dst * 4];
    float w0 = ex.x * inv.x;
    float w1 = ex.y * inv.y;
    float w2 = ex.z * inv.z;
    float w3 = ex.w * inv.w;

    int c0 = l * 4;                // 4 channels per lane
    const __half* hb = &g_hh[src * HC];
    uint2 u0 = *(const uint2*)&hb[c0];
    uint2 u1 = *(const uint2*)&hb[64 + c0];
    uint2 u2 = *(const uint2*)&hb[128 + c0];
    uint2 u3 = *(const uint2*)&hb[192 + c0];
    float2 a0 = __half22float2(*(__half2*)&u0.x), b0 = __half22float2(*(__half2*)&u0.y);
    float2 a1 = __half22float2(*(__half2*)&u1.x), b1 = __half22float2(*(__half2*)&u1.y);
    float2 a2 = __half22float2(*(__half2*)&u2.x), b2 = __half22float2(*(__half2*)&u2.y);
    float2 a3 = __half22float2(*(__half2*)&u3.x), b3 = __half22float2(*(__half2*)&u3.y);

    float4 m;
    m.x = w0 * a0.x + w1 * a1.x + w2 * a2.x + w3 * a3.x;
    m.y = w0 * a0.y + w1 * a1.y + w2 * a2.y + w3 * a3.y;
    m.z = w0 * b0.x + w1 * b1.x + w2 * b2.x + w3 * b3.x;
    m.w = w0 * b0.y + w1 * b1.y + w2 * b2.y + w3 * b3.y;
    atomicAdd((float4*)&g_acc[dst * OUT_DIM + c0], m);
}

// ---------------- K5: out = relu(x_conv @ Wc[:64] + t)  (4 nodes/block) -------
__global__ void k5_out(const float* __restrict__ Wc,
                       const float* __restrict__ bias,
                       float* __restrict__ out) {
    __shared__ float xc[4][OUT_DIM];
    int t = threadIdx.x;
    int nl = t >> 6, j = t & 63;
    int n = blockIdx.x * 4 + nl;
    xc[nl][j] = g_acc[n * OUT_DIM + j] + bias[j];
    __syncthreads();
    float s = g_t[j];
    #pragma unroll 8
    for (int c = 0; c < OUT_DIM; ++c)
        s += xc[nl][c] * Wc[c * 64 + j];
    out[n * OUT_DIM + j] = fmaxf(s, 0.f);
}

// ---------------- launch ----------------
extern "C" void kernel_launch(void* const* d_in, const int* in_sizes, int n_in,
                              void* d_out, int out_size) {
    const float* x         = (const float*)d_in[0];
    const void*  ei        = d_in[1];
    const float* edge_attr = (const float*)d_in[2];
    const float* pq        = (const float*)d_in[3];
    const float* ns        = (const float*)d_in[4];
    const float* W         = (const float*)d_in[5];
    const float* att_src   = (const float*)d_in[6];
    const float* att_dst   = (const float*)d_in[7];
    const float* W_edge    = (const float*)d_in[8];
    const float* att_edge  = (const float*)d_in[9];
    const float* bias      = (const float*)d_in[10];
    const float* Wq1       = (const float*)d_in[11];
    const float* bq1       = (const float*)d_in[12];
    const float* Wq2       = (const float*)d_in[13];
    const float* bq2       = (const float*)d_in[14];
    const float* Wc        = (const float*)d_in[15];
    const float* bc        = (const float*)d_in[16];
    float* out = (float*)d_out;

    k_wcvt_pre<<<129, 256>>>(W, W_edge, att_edge, Wq1, bq1, Wq2, bq2,
                             ns, Wc, bc, ei);                            // idx 0
    k_xcvt<<<(N_NODES * IN_DIM / 8 + 255) / 256, 256>>>(x);              // idx 1
    k1_mma<<<(N_NODES + 63) / 64, 256>>>(att_src, att_dst);              // idx 2
    k2_edge<<<E_EDGES / EPB, 256>>>(ei, edge_attr, pq);                  // idx 3 (profiled)
    k3_invden<<<(N_NODES * HEADS + 255) / 256, 256>>>();                 // idx 4
    k4_aggregate<<<(E_EDGES * 16 + 255) / 256, 256>>>(ei);               // idx 5
    k5_out<<<N_NODES / 4, 256>>>(Wc, bias, out);                         // idx 6
}